// round 1
// baseline (speedup 1.0000x reference)
#include <cuda_runtime.h>
#include <cuda_bf16.h>
#include <cstdint>

// Problem dims
#define N_INST 128
#define N_NOTES 88
#define BATCH 64
#define TLEN 201
#define FLEN 52
#define T1 199  // conv1 out rows
#define F1 50   // conv1 out cols
#define T2 197  // conv2 out rows
#define F2 48   // conv2 out cols
#define FEAT (T2 * F2)  // 9456

// Scratch for X = relu(conv2(relu(conv1(data)))) in [i][b][f] layout
__device__ float g_X[(size_t)N_INST * BATCH * FEAT];

// ---------------------------------------------------------------------------
// Conv kernel: one CTA per (instrument, batch). 64 threads.
// Column-per-thread sliding window; 3-row shared ring buffer between convs.
// ---------------------------------------------------------------------------
__global__ __launch_bounds__(64) void conv_kernel(
    const float* __restrict__ data,
    const float* __restrict__ w1, const float* __restrict__ b1,
    const float* __restrict__ w2, const float* __restrict__ b2)
{
    const int i = blockIdx.x;   // instrument
    const int b = blockIdx.y;   // batch
    const int j = threadIdx.x;  // column

    __shared__ float ring[3][F1 + 2];  // conv1 rows (50 used)

    float W1[9], W2[9];
#pragma unroll
    for (int k = 0; k < 9; ++k) {
        W1[k] = w1[i * 9 + k];
        W2[k] = w2[i * 9 + k];
    }
    const float B1 = b1[i];
    const float B2 = b2[i];

    const float* dptr = data + (size_t)b * TLEN * FLEN;
    float* xptr = g_X + ((size_t)i * BATCH + b) * FEAT;

    // conv1 input window (data rows), conv2 input window (conv1 rows)
    float d0[3], d1[3], d2[3];
    float c0[3], c1[3], c2[3];
#pragma unroll
    for (int k = 0; k < 3; ++k) { d0[k] = 0.f; d1[k] = 0.f; c0[k] = 0.f; c1[k] = 0.f; }

    if (j < F1) {
#pragma unroll
        for (int k = 0; k < 3; ++k) {
            d0[k] = dptr[0 * FLEN + j + k];
            d1[k] = dptr[1 * FLEN + j + k];
        }
    }

    for (int t = 0; t < T1; ++t) {
        // --- conv1 row t (needs data rows t..t+2) ---
        if (j < F1) {
#pragma unroll
            for (int k = 0; k < 3; ++k) d2[k] = dptr[(t + 2) * FLEN + j + k];
            float v = B1;
            v = fmaf(W1[0], d0[0], v); v = fmaf(W1[1], d0[1], v); v = fmaf(W1[2], d0[2], v);
            v = fmaf(W1[3], d1[0], v); v = fmaf(W1[4], d1[1], v); v = fmaf(W1[5], d1[2], v);
            v = fmaf(W1[6], d2[0], v); v = fmaf(W1[7], d2[1], v); v = fmaf(W1[8], d2[2], v);
            v = fmaxf(v, 0.f);
            ring[t % 3][j] = v;
        }
        __syncthreads();

        // --- conv2 consumes conv1 rows; output row t-2 ---
        if (j < F2) {
#pragma unroll
            for (int k = 0; k < 3; ++k) c2[k] = ring[t % 3][j + k];
            if (t >= 2) {
                float u = B2;
                u = fmaf(W2[0], c0[0], u); u = fmaf(W2[1], c0[1], u); u = fmaf(W2[2], c0[2], u);
                u = fmaf(W2[3], c1[0], u); u = fmaf(W2[4], c1[1], u); u = fmaf(W2[5], c1[2], u);
                u = fmaf(W2[6], c2[0], u); u = fmaf(W2[7], c2[1], u); u = fmaf(W2[8], c2[2], u);
                u = fmaxf(u, 0.f);
                xptr[(t - 2) * F2 + j] = u;
            }
#pragma unroll
            for (int k = 0; k < 3; ++k) { c0[k] = c1[k]; c1[k] = c2[k]; }
        }
        __syncthreads();

#pragma unroll
        for (int k = 0; k < 3; ++k) { d0[k] = d1[k]; d1[k] = d2[k]; }
    }
}

// ---------------------------------------------------------------------------
// FC kernel: one CTA per instrument. out[b,i,n] = sigmoid(X[i,b,:]·wfc[i,n,:]+bfc)
// CTA tile 64(m=batch) x 96(n padded from 88). 256 threads, thread tile 4x6.
// K chunks of 48 (9456 = 197*48). Packed f32x2 FMAs along K.
// ---------------------------------------------------------------------------
#define KC 48
#define XS_STRIDE 50
#define WS_STRIDE 50

__device__ __forceinline__ unsigned long long ffma2(
    unsigned long long a, unsigned long long b, unsigned long long c)
{
    unsigned long long d;
    asm("fma.rn.f32x2 %0, %1, %2, %3;" : "=l"(d) : "l"(a), "l"(b), "l"(c));
    return d;
}

__global__ __launch_bounds__(256) void fc_kernel(
    const float* __restrict__ wfc,
    const float* __restrict__ bfc,
    float* __restrict__ out)
{
    const int i = blockIdx.x;
    const int tid = threadIdx.x;
    const int tx = tid & 15;   // n group
    const int ty = tid >> 4;   // m group

    __shared__ float Xs[BATCH * XS_STRIDE];
    __shared__ float Ws[96 * WS_STRIDE];

    // zero the padded note rows 88..95 (never written in the loop)
    for (int idx = tid; idx < 8 * KC; idx += 256) {
        int n = 88 + idx / KC;
        int k = idx % KC;
        Ws[n * WS_STRIDE + k] = 0.f;
    }

    unsigned long long acc[4][6];
#pragma unroll
    for (int mm = 0; mm < 4; ++mm)
#pragma unroll
        for (int nn = 0; nn < 6; ++nn) acc[mm][nn] = 0ull;

    const float* Xp = g_X + (size_t)i * BATCH * FEAT;
    const float* Wp = wfc + (size_t)i * N_NOTES * FEAT;

    for (int ch = 0; ch < FEAT / KC; ++ch) {
        const int k0 = ch * KC;
        __syncthreads();
        // load X tile: 64 rows x 24 float2
        for (int idx = tid; idx < BATCH * (KC / 2); idx += 256) {
            int r = idx / (KC / 2), q = idx % (KC / 2);
            *(float2*)&Xs[r * XS_STRIDE + q * 2] =
                *(const float2*)&Xp[(size_t)r * FEAT + k0 + q * 2];
        }
        // load W tile: 88 rows x 24 float2
        for (int idx = tid; idx < N_NOTES * (KC / 2); idx += 256) {
            int r = idx / (KC / 2), q = idx % (KC / 2);
            *(float2*)&Ws[r * WS_STRIDE + q * 2] =
                *(const float2*)&Wp[(size_t)r * FEAT + k0 + q * 2];
        }
        __syncthreads();

#pragma unroll 6
        for (int kp = 0; kp < KC / 2; ++kp) {
            unsigned long long xv[4], wv[6];
#pragma unroll
            for (int mm = 0; mm < 4; ++mm)
                xv[mm] = *(const unsigned long long*)&Xs[(mm * 16 + ty) * XS_STRIDE + kp * 2];
#pragma unroll
            for (int nn = 0; nn < 6; ++nn)
                wv[nn] = *(const unsigned long long*)&Ws[(nn * 16 + tx) * WS_STRIDE + kp * 2];
#pragma unroll
            for (int mm = 0; mm < 4; ++mm)
#pragma unroll
                for (int nn = 0; nn < 6; ++nn)
                    acc[mm][nn] = ffma2(xv[mm], wv[nn], acc[mm][nn]);
        }
    }

    // epilogue: horizontal add, bias, sigmoid, store
#pragma unroll
    for (int mm = 0; mm < 4; ++mm) {
        int m = mm * 16 + ty;  // batch index
#pragma unroll
        for (int nn = 0; nn < 6; ++nn) {
            int n = nn * 16 + tx;
            if (n < N_NOTES) {
                float2 av = *reinterpret_cast<float2*>(&acc[mm][nn]);
                float s = av.x + av.y + bfc[i * N_NOTES + n];
                float r = 1.f / (1.f + __expf(-s));
                out[((size_t)m * N_INST + i) * N_NOTES + n] = r;
            }
        }
    }
}

// ---------------------------------------------------------------------------
extern "C" void kernel_launch(void* const* d_in, const int* in_sizes, int n_in,
                              void* d_out, int out_size)
{
    const float* data = (const float*)d_in[0];
    const float* w1   = (const float*)d_in[1];
    const float* b1   = (const float*)d_in[2];
    const float* w2   = (const float*)d_in[3];
    const float* b2   = (const float*)d_in[4];
    const float* wfc  = (const float*)d_in[5];
    const float* bfc  = (const float*)d_in[6];
    float* out = (float*)d_out;

    dim3 cgrid(N_INST, BATCH);
    conv_kernel<<<cgrid, 64>>>(data, w1, b1, w2, b2);
    fc_kernel<<<N_INST, 256>>>(wfc, bfc, out);
}

// round 3
// speedup vs baseline: 2.6787x; 2.6787x over previous
#include <cuda_runtime.h>
#include <cuda_bf16.h>
#include <cstdint>

// Problem dims
#define N_INST 128
#define N_NOTES 88
#define BATCH 64
#define TLEN 201
#define FLEN 52
#define T1 199
#define F1 50
#define T2 197
#define F2 48
#define FEAT (T2 * F2)  // 9456
#define KC 48
#define NCHUNK 197

// X split into bf16 hi/lo planes, [i][b][k]
__device__ __nv_bfloat16 g_Xhi[(size_t)N_INST * BATCH * FEAT];
__device__ __nv_bfloat16 g_Xlo[(size_t)N_INST * BATCH * FEAT];

// ---------------------------------------------------------------------------
// helpers
// ---------------------------------------------------------------------------
__device__ __forceinline__ uint32_t smem_u32(const void* p) {
    uint32_t a;
    asm("{ .reg .u64 t; cvta.to.shared.u64 t, %1; cvt.u32.u64 %0, t; }" : "=r"(a) : "l"(p));
    return a;
}
__device__ __forceinline__ unsigned swz(unsigned off) { return off ^ ((off >> 3) & 0x70); }

__device__ __forceinline__ void cp16(uint32_t dst, const void* src) {
    asm volatile("cp.async.ca.shared.global [%0], [%1], 16;" :: "r"(dst), "l"(src) : "memory");
}
__device__ __forceinline__ void cp_commit() { asm volatile("cp.async.commit_group;" ::: "memory"); }
__device__ __forceinline__ void cp_wait0()  { asm volatile("cp.async.wait_group 0;" ::: "memory"); }

__device__ __forceinline__ void ldsm4(unsigned r[4], uint32_t a) {
    asm volatile("ldmatrix.sync.aligned.m8n8.x4.shared.b16 {%0,%1,%2,%3}, [%4];"
                 : "=r"(r[0]), "=r"(r[1]), "=r"(r[2]), "=r"(r[3]) : "r"(a));
}
__device__ __forceinline__ void ldsm2(unsigned r[2], uint32_t a) {
    asm volatile("ldmatrix.sync.aligned.m8n8.x2.shared.b16 {%0,%1}, [%2];"
                 : "=r"(r[0]), "=r"(r[1]) : "r"(a));
}
__device__ __forceinline__ void mma_bf16(float c[4], const unsigned a[4], const unsigned b[2]) {
    asm volatile(
        "mma.sync.aligned.m16n8k16.row.col.f32.bf16.bf16.f32 "
        "{%0,%1,%2,%3}, {%4,%5,%6,%7}, {%8,%9}, {%0,%1,%2,%3};"
        : "+f"(c[0]), "+f"(c[1]), "+f"(c[2]), "+f"(c[3])
        : "r"(a[0]), "r"(a[1]), "r"(a[2]), "r"(a[3]), "r"(b[0]), "r"(b[1]));
}
__device__ __forceinline__ unsigned pack_bf16x2(float x, float y) {
    __nv_bfloat16 hx = __float2bfloat16(x), hy = __float2bfloat16(y);
    return (unsigned)__bfloat16_as_ushort(hx) | ((unsigned)__bfloat16_as_ushort(hy) << 16);
}

// ---------------------------------------------------------------------------
// Conv kernel: 128 threads = 2 batch images per CTA. Emits bf16 hi/lo planes.
// ---------------------------------------------------------------------------
__global__ __launch_bounds__(128) void conv_kernel(
    const float* __restrict__ data,
    const float* __restrict__ w1, const float* __restrict__ b1,
    const float* __restrict__ w2, const float* __restrict__ b2)
{
    const int i = blockIdx.x;
    const int sub = threadIdx.x >> 6;
    const int j = threadIdx.x & 63;
    const int b = blockIdx.y * 2 + sub;

    __shared__ float ring[2][3][F1 + 2];

    float W1[9], W2[9];
#pragma unroll
    for (int k = 0; k < 9; ++k) { W1[k] = w1[i * 9 + k]; W2[k] = w2[i * 9 + k]; }
    const float B1 = b1[i];
    const float B2 = b2[i];

    const float* dptr = data + (size_t)b * TLEN * FLEN;
    __nv_bfloat16* xh = g_Xhi + ((size_t)i * BATCH + b) * FEAT;
    __nv_bfloat16* xl = g_Xlo + ((size_t)i * BATCH + b) * FEAT;

    float d0[3], d1[3], d2[3];
    float c0[3], c1[3], c2[3];
#pragma unroll
    for (int k = 0; k < 3; ++k) { d0[k] = 0.f; d1[k] = 0.f; c0[k] = 0.f; c1[k] = 0.f; }

    if (j < F1) {
#pragma unroll
        for (int k = 0; k < 3; ++k) {
            d0[k] = dptr[0 * FLEN + j + k];
            d1[k] = dptr[1 * FLEN + j + k];
        }
    }

    for (int t = 0; t < T1; ++t) {
        if (j < F1) {
#pragma unroll
            for (int k = 0; k < 3; ++k) d2[k] = dptr[(t + 2) * FLEN + j + k];
            float v = B1;
            v = fmaf(W1[0], d0[0], v); v = fmaf(W1[1], d0[1], v); v = fmaf(W1[2], d0[2], v);
            v = fmaf(W1[3], d1[0], v); v = fmaf(W1[4], d1[1], v); v = fmaf(W1[5], d1[2], v);
            v = fmaf(W1[6], d2[0], v); v = fmaf(W1[7], d2[1], v); v = fmaf(W1[8], d2[2], v);
            ring[sub][t % 3][j] = fmaxf(v, 0.f);
        }
        __syncthreads();

        if (j < F2) {
#pragma unroll
            for (int k = 0; k < 3; ++k) c2[k] = ring[sub][t % 3][j + k];
            if (t >= 2) {
                float u = B2;
                u = fmaf(W2[0], c0[0], u); u = fmaf(W2[1], c0[1], u); u = fmaf(W2[2], c0[2], u);
                u = fmaf(W2[3], c1[0], u); u = fmaf(W2[4], c1[1], u); u = fmaf(W2[5], c1[2], u);
                u = fmaf(W2[6], c2[0], u); u = fmaf(W2[7], c2[1], u); u = fmaf(W2[8], c2[2], u);
                u = fmaxf(u, 0.f);
                __nv_bfloat16 h = __float2bfloat16(u);
                __nv_bfloat16 l = __float2bfloat16(u - __bfloat162float(h));
                xh[(t - 2) * F2 + j] = h;
                xl[(t - 2) * F2 + j] = l;
            }
#pragma unroll
            for (int k = 0; k < 3; ++k) { c0[k] = c1[k]; c1[k] = c2[k]; }
        }
        __syncthreads();

#pragma unroll
        for (int k = 0; k < 3; ++k) { d0[k] = d1[k]; d1[k] = d2[k]; }
    }
}

// ---------------------------------------------------------------------------
// FC kernel: one CTA / instrument. mma.sync bf16, 3-term hi/lo, double buffer.
// CTA tile 64(b) x 96(n pad of 88). 8 warps (2x4), warp tile 32x24.
// smem tile rows padded to 128B with SW128 swizzle.
// ---------------------------------------------------------------------------
#define XHI_OFF 0
#define XLO_OFF 8192
#define WHI_OFF 16384
#define WLO_OFF 28672
#define BUF_BYTES 40960
#define SMEM_TOTAL (2 * BUF_BYTES)

__global__ __launch_bounds__(256, 1) void fc_kernel(
    const float* __restrict__ wfc,
    const float* __restrict__ bfc,
    float* __restrict__ out)
{
    extern __shared__ char sm[];
    const uint32_t sbase = smem_u32(sm);
    const int i = blockIdx.x;
    const int tid = threadIdx.x;
    const int lane = tid & 31;
    const int wid = tid >> 5;
    const int warp_m = wid >> 2;   // 0..1 -> batch offset *32
    const int warp_n = wid & 3;    // 0..3 -> note offset *24

    // zero smem once (covers W pad rows 88..95, never written later)
    for (int o = tid * 16; o < SMEM_TOTAL; o += 256 * 16)
        *(uint4*)(sm + o) = make_uint4(0, 0, 0, 0);
    __syncthreads();

    const float* Wp = wfc + (size_t)i * N_NOTES * FEAT;
    const __nv_bfloat16* Xhp = g_Xhi + (size_t)i * BATCH * FEAT;
    const __nv_bfloat16* Xlp = g_Xlo + (size_t)i * BATCH * FEAT;

    // W staging: 1056 float4 per chunk (88 rows x 12), 5 per thread
    float4 wreg[5];
    int widx[5], wrow[5], wq[5];
#pragma unroll
    for (int s = 0; s < 5; ++s) {
        widx[s] = tid + s * 256;
        wrow[s] = widx[s] / 12;
        wq[s] = widx[s] % 12;
    }

    auto stage_w = [&](int c) {
        const int k0 = c * KC;
#pragma unroll
        for (int s = 0; s < 5; ++s)
            if (widx[s] < N_NOTES * 12)
                wreg[s] = *(const float4*)(Wp + (size_t)wrow[s] * FEAT + k0 + wq[s] * 4);
    };
    auto sts_w = [&](int buf) {
        char* base = sm + buf * BUF_BYTES;
#pragma unroll
        for (int s = 0; s < 5; ++s) {
            if (widx[s] < N_NOTES * 12) {
                float4 v = wreg[s];
                unsigned hi0 = pack_bf16x2(v.x, v.y);
                float lx = v.x - __bfloat162float(__float2bfloat16(v.x));
                float ly = v.y - __bfloat162float(__float2bfloat16(v.y));
                unsigned lo0 = pack_bf16x2(lx, ly);
                unsigned hi1 = pack_bf16x2(v.z, v.w);
                float lz = v.z - __bfloat162float(__float2bfloat16(v.z));
                float lw = v.w - __bfloat162float(__float2bfloat16(v.w));
                unsigned lo1 = pack_bf16x2(lz, lw);
                unsigned off = swz(wrow[s] * 128 + wq[s] * 8);
                *(uint2*)(base + WHI_OFF + off) = make_uint2(hi0, hi1);
                *(uint2*)(base + WLO_OFF + off) = make_uint2(lo0, lo1);
            }
        }
    };
    // X cp.async: 768 x 16B per chunk (hi 384 + lo 384), 3 per thread
    auto cpa_x = [&](int c, int buf) {
        const int k0 = c * KC;
#pragma unroll
        for (int s = 0; s < 3; ++s) {
            int idx = tid + s * 256;
            int half = idx >= 384;
            int e = half ? idx - 384 : idx;
            int r = e / 6, q = e % 6;
            const __nv_bfloat16* src =
                (half ? Xlp : Xhp) + (size_t)r * FEAT + k0 + q * 8;
            uint32_t dst = sbase + buf * BUF_BYTES + (half ? XLO_OFF : XHI_OFF) +
                           swz(r * 128 + q * 16);
            cp16(dst, src);
        }
        cp_commit();
    };

    float acc[2][3][4];
#pragma unroll
    for (int mt = 0; mt < 2; ++mt)
#pragma unroll
        for (int nt = 0; nt < 3; ++nt)
#pragma unroll
            for (int r = 0; r < 4; ++r) acc[mt][nt][r] = 0.f;

    // per-lane ldmatrix offsets
    const int a_row = lane & 15;
    const int a_colb = (lane >> 4) << 4;        // 0 or 16 bytes (k +8 elems)
    const int bl15 = lane & 15;
    const int b_row = bl15 & 7;
    const int b_colb = (bl15 >> 3) << 4;

    // prologue
    stage_w(0);
    cpa_x(0, 0);

    for (int c = 0; c < NCHUNK; ++c) {
        const int buf = c & 1;
        sts_w(buf);
        cp_wait0();
        __syncthreads();
        if (c + 1 < NCHUNK) {
            stage_w(c + 1);
            cpa_x(c + 1, buf ^ 1);
        }

        const uint32_t tb = sbase + buf * BUF_BYTES;
#pragma unroll
        for (int ks = 0; ks < 3; ++ks) {
            const int kb = ks * 32;  // 16 elems * 2B
            unsigned ahi[2][4], alo[2][4];
#pragma unroll
            for (int mt = 0; mt < 2; ++mt) {
                int m0 = warp_m * 32 + mt * 16;
                unsigned off = swz((m0 + a_row) * 128 + kb + a_colb);
                ldsm4(ahi[mt], tb + XHI_OFF + off);
                ldsm4(alo[mt], tb + XLO_OFF + off);
            }
#pragma unroll
            for (int nt = 0; nt < 3; ++nt) {
                int n0 = warp_n * 24 + nt * 8;
                unsigned off = swz((n0 + b_row) * 128 + kb + b_colb);
                unsigned bh[2], bl[2];
                ldsm2(bh, tb + WHI_OFF + off);
                ldsm2(bl, tb + WLO_OFF + off);
#pragma unroll
                for (int mt = 0; mt < 2; ++mt) {
                    mma_bf16(acc[mt][nt], ahi[mt], bh);
                    mma_bf16(acc[mt][nt], ahi[mt], bl);
                    mma_bf16(acc[mt][nt], alo[mt], bh);
                }
            }
        }
    }

    // epilogue: bias + sigmoid + store out[b][i][n]
#pragma unroll
    for (int mt = 0; mt < 2; ++mt) {
        int b0 = warp_m * 32 + mt * 16 + (lane >> 2);
#pragma unroll
        for (int nt = 0; nt < 3; ++nt) {
            int n = warp_n * 24 + nt * 8 + 2 * (lane & 3);
            if (n < N_NOTES) {
                float bi0 = bfc[i * N_NOTES + n];
                float bi1 = bfc[i * N_NOTES + n + 1];
                float s0 = acc[mt][nt][0] + bi0;
                float s1 = acc[mt][nt][1] + bi1;
                float s2 = acc[mt][nt][2] + bi0;
                float s3 = acc[mt][nt][3] + bi1;
                float2 r0 = make_float2(1.f / (1.f + __expf(-s0)), 1.f / (1.f + __expf(-s1)));
                float2 r1 = make_float2(1.f / (1.f + __expf(-s2)), 1.f / (1.f + __expf(-s3)));
                *(float2*)(out + ((size_t)b0 * N_INST + i) * N_NOTES + n) = r0;
                *(float2*)(out + ((size_t)(b0 + 8) * N_INST + i) * N_NOTES + n) = r1;
            }
        }
    }
}

// ---------------------------------------------------------------------------
extern "C" void kernel_launch(void* const* d_in, const int* in_sizes, int n_in,
                              void* d_out, int out_size)
{
    const float* data = (const float*)d_in[0];
    const float* w1   = (const float*)d_in[1];
    const float* b1   = (const float*)d_in[2];
    const float* w2   = (const float*)d_in[3];
    const float* b2   = (const float*)d_in[4];
    const float* wfc  = (const float*)d_in[5];
    const float* bfc  = (const float*)d_in[6];
    float* out = (float*)d_out;

    cudaFuncSetAttribute(fc_kernel, cudaFuncAttributeMaxDynamicSharedMemorySize, SMEM_TOTAL);

    dim3 cgrid(N_INST, BATCH / 2);
    conv_kernel<<<cgrid, 128>>>(data, w1, b1, w2, b2);
    fc_kernel<<<N_INST, 256, SMEM_TOTAL>>>(wfc, bfc, out);
}

// round 4
// speedup vs baseline: 3.3941x; 1.2671x over previous
#include <cuda_runtime.h>
#include <cuda_bf16.h>
#include <cstdint>

// Problem dims
#define N_INST 128
#define N_NOTES 88
#define BATCH 64
#define TLEN 201
#define FLEN 52
#define T1 199
#define F1 50
#define T2 197
#define F2 48
#define FEAT (T2 * F2)  // 9456
#define KC 48
#define NCHUNK 197

// X split into bf16 hi/lo planes, [i][b][k]
__device__ __nv_bfloat16 g_Xhi[(size_t)N_INST * BATCH * FEAT];
__device__ __nv_bfloat16 g_Xlo[(size_t)N_INST * BATCH * FEAT];

// ---------------------------------------------------------------------------
// helpers
// ---------------------------------------------------------------------------
__device__ __forceinline__ uint32_t smem_u32(const void* p) {
    uint32_t a;
    asm("{ .reg .u64 t; cvta.to.shared.u64 t, %1; cvt.u32.u64 %0, t; }" : "=r"(a) : "l"(p));
    return a;
}
__device__ __forceinline__ unsigned swz(unsigned off) { return off ^ ((off >> 3) & 0x70); }

__device__ __forceinline__ void cp16(uint32_t dst, const void* src) {
    asm volatile("cp.async.ca.shared.global [%0], [%1], 16;" :: "r"(dst), "l"(src) : "memory");
}
__device__ __forceinline__ void cp_commit() { asm volatile("cp.async.commit_group;" ::: "memory"); }
__device__ __forceinline__ void cp_wait0()  { asm volatile("cp.async.wait_group 0;" ::: "memory"); }

__device__ __forceinline__ void ldsm4(unsigned r[4], uint32_t a) {
    asm volatile("ldmatrix.sync.aligned.m8n8.x4.shared.b16 {%0,%1,%2,%3}, [%4];"
                 : "=r"(r[0]), "=r"(r[1]), "=r"(r[2]), "=r"(r[3]) : "r"(a));
}
__device__ __forceinline__ void ldsm2(unsigned r[2], uint32_t a) {
    asm volatile("ldmatrix.sync.aligned.m8n8.x2.shared.b16 {%0,%1}, [%2];"
                 : "=r"(r[0]), "=r"(r[1]) : "r"(a));
}
__device__ __forceinline__ void mma_bf16(float c[4], const unsigned a[4], const unsigned* b) {
    asm volatile(
        "mma.sync.aligned.m16n8k16.row.col.f32.bf16.bf16.f32 "
        "{%0,%1,%2,%3}, {%4,%5,%6,%7}, {%8,%9}, {%0,%1,%2,%3};"
        : "+f"(c[0]), "+f"(c[1]), "+f"(c[2]), "+f"(c[3])
        : "r"(a[0]), "r"(a[1]), "r"(a[2]), "r"(a[3]), "r"(b[0]), "r"(b[1]));
}
// pack bf16x2 with RN: low half = lo, high half = hi
__device__ __forceinline__ unsigned cvt_bf16x2(float lo, float hi) {
    unsigned d;
    asm("cvt.rn.bf16x2.f32 %0, %1, %2;" : "=r"(d) : "f"(hi), "f"(lo));
    return d;
}

// ---------------------------------------------------------------------------
// Conv kernel: barrier-free, one warp = (instrument, batch, column-half).
// Sliding 3x3 register windows + warp shuffles. Emits bf16 hi/lo planes.
// ---------------------------------------------------------------------------
__global__ __launch_bounds__(256) void conv_kernel(
    const float* __restrict__ data,
    const float* __restrict__ w1, const float* __restrict__ b1,
    const float* __restrict__ w2, const float* __restrict__ b2)
{
    const int wid = threadIdx.x >> 5;
    const int lane = threadIdx.x & 31;
    const int g = blockIdx.x * 8 + wid;   // 0..16383
    const int h = g & 1;
    const int p = g >> 1;                 // (i,b) pair
    const int i = p >> 6;
    const int b = p & 63;

    const int col = h * 28 + lane;              // data / conv1 column
    const int cl = col > 51 ? 51 : col;         // clamped load column
    const bool do_store = h == 0 ? (lane < 28) : (lane < 20);

    float W1[9], W2[9];
#pragma unroll
    for (int k = 0; k < 9; ++k) { W1[k] = w1[i * 9 + k]; W2[k] = w2[i * 9 + k]; }
    const float B1 = b1[i];
    const float B2 = b2[i];

    const float* dptr = data + (size_t)b * TLEN * FLEN;
    unsigned short* xh = (unsigned short*)(g_Xhi + ((size_t)i * BATCH + b) * FEAT);
    unsigned short* xl = (unsigned short*)(g_Xlo + ((size_t)i * BATCH + b) * FEAT);

    float dw[3][3];  // data rows (t%3) x 3 cols
    float cw[3][3];  // conv1 rows (t%3) x 3 cols

    // preload data rows 0,1
#pragma unroll
    for (int r = 0; r < 2; ++r) {
        float x = dptr[r * FLEN + cl];
        dw[r][0] = x;
        dw[r][1] = __shfl_down_sync(0xffffffffu, x, 1);
        dw[r][2] = __shfl_down_sync(0xffffffffu, x, 2);
    }

#pragma unroll 3
    for (int t = 0; t < T1; ++t) {
        const int r2 = (t + 2) % 3;
        const int r0 = t % 3;
        const int r1 = (t + 1) % 3;

        float x = dptr[(t + 2) * FLEN + cl];
        dw[r2][0] = x;
        dw[r2][1] = __shfl_down_sync(0xffffffffu, x, 1);
        dw[r2][2] = __shfl_down_sync(0xffffffffu, x, 2);

        // conv1 at (row t, col)
        float v = B1;
        v = fmaf(W1[0], dw[r0][0], v); v = fmaf(W1[1], dw[r0][1], v); v = fmaf(W1[2], dw[r0][2], v);
        v = fmaf(W1[3], dw[r1][0], v); v = fmaf(W1[4], dw[r1][1], v); v = fmaf(W1[5], dw[r1][2], v);
        v = fmaf(W1[6], dw[r2][0], v); v = fmaf(W1[7], dw[r2][1], v); v = fmaf(W1[8], dw[r2][2], v);
        v = fmaxf(v, 0.f);

        cw[r0][0] = v;  // row t stored in slot t%3 (overwrites row t-3)
        cw[r0][1] = __shfl_down_sync(0xffffffffu, v, 1);
        cw[r0][2] = __shfl_down_sync(0xffffffffu, v, 2);

        if (t >= 2) {
            // conv2 output row t-2 needs conv1 rows t-2,t-1,t = slots r1, r2, r0
            float u = B2;
            u = fmaf(W2[0], cw[r1][0], u); u = fmaf(W2[1], cw[r1][1], u); u = fmaf(W2[2], cw[r1][2], u);
            u = fmaf(W2[3], cw[r2][0], u); u = fmaf(W2[4], cw[r2][1], u); u = fmaf(W2[5], cw[r2][2], u);
            u = fmaf(W2[6], cw[r0][0], u); u = fmaf(W2[7], cw[r0][1], u); u = fmaf(W2[8], cw[r0][2], u);
            u = fmaxf(u, 0.f);
            if (do_store) {
                unsigned ub = __float_as_uint(u);
                float rem = u - __uint_as_float(ub & 0xffff0000u);
                int idx = (t - 2) * F2 + col;
                xh[idx] = (unsigned short)(ub >> 16);
                xl[idx] = __bfloat16_as_ushort(__float2bfloat16(rem));
            }
        }
    }
}

// ---------------------------------------------------------------------------
// FC kernel: one CTA / instrument. mma.sync bf16, 3-term hi/lo, double buffer.
// ---------------------------------------------------------------------------
#define XHI_OFF 0
#define XLO_OFF 8192
#define WHI_OFF 16384
#define WLO_OFF 28672
#define BUF_BYTES 40960
#define SMEM_TOTAL (2 * BUF_BYTES)

__global__ __launch_bounds__(256, 1) void fc_kernel(
    const float* __restrict__ wfc,
    const float* __restrict__ bfc,
    float* __restrict__ out)
{
    extern __shared__ char sm[];
    const uint32_t sbase = smem_u32(sm);
    const int i = blockIdx.x;
    const int tid = threadIdx.x;
    const int lane = tid & 31;
    const int wid = tid >> 5;
    const int warp_m = wid >> 2;   // 0..1 -> batch offset *32
    const int warp_n = wid & 3;    // 0..3 -> note offset *24

    // zero smem once (covers W pad rows 88..95, never written later)
    for (int o = tid * 16; o < SMEM_TOTAL; o += 256 * 16)
        *(uint4*)(sm + o) = make_uint4(0, 0, 0, 0);
    __syncthreads();

    const float* Wp = wfc + (size_t)i * N_NOTES * FEAT;
    const __nv_bfloat16* Xhp = g_Xhi + (size_t)i * BATCH * FEAT;
    const __nv_bfloat16* Xlp = g_Xlo + (size_t)i * BATCH * FEAT;

    // W staging: 1056 float4 per chunk (88 rows x 12), 5 per thread
    float4 wreg[5];
    int widx[5], wrow[5], wq[5];
#pragma unroll
    for (int s = 0; s < 5; ++s) {
        widx[s] = tid + s * 256;
        wrow[s] = widx[s] / 12;
        wq[s] = widx[s] % 12;
    }

    auto stage_w = [&](int c) {
        const int k0 = c * KC;
#pragma unroll
        for (int s = 0; s < 5; ++s)
            if (widx[s] < N_NOTES * 12)
                wreg[s] = *(const float4*)(Wp + (size_t)wrow[s] * FEAT + k0 + wq[s] * 4);
    };
    auto sts_w = [&](int buf) {
        char* base = sm + buf * BUF_BYTES;
#pragma unroll
        for (int s = 0; s < 5; ++s) {
            if (widx[s] < N_NOTES * 12) {
                float4 v = wreg[s];
                unsigned ax = __float_as_uint(v.x), ay = __float_as_uint(v.y);
                unsigned az = __float_as_uint(v.z), aw = __float_as_uint(v.w);
                unsigned hi0 = __byte_perm(ax, ay, 0x7632);
                unsigned hi1 = __byte_perm(az, aw, 0x7632);
                float rx = v.x - __uint_as_float(ax & 0xffff0000u);
                float ry = v.y - __uint_as_float(ay & 0xffff0000u);
                float rz = v.z - __uint_as_float(az & 0xffff0000u);
                float rw = v.w - __uint_as_float(aw & 0xffff0000u);
                unsigned lo0 = cvt_bf16x2(rx, ry);
                unsigned lo1 = cvt_bf16x2(rz, rw);
                unsigned off = swz(wrow[s] * 128 + wq[s] * 8);
                *(uint2*)(base + WHI_OFF + off) = make_uint2(hi0, hi1);
                *(uint2*)(base + WLO_OFF + off) = make_uint2(lo0, lo1);
            }
        }
    };
    // X cp.async: 768 x 16B per chunk (hi 384 + lo 384), 3 per thread
    auto cpa_x = [&](int c, int buf) {
        const int k0 = c * KC;
#pragma unroll
        for (int s = 0; s < 3; ++s) {
            int idx = tid + s * 256;
            int half = idx >= 384;
            int e = half ? idx - 384 : idx;
            int r = e / 6, q = e % 6;
            const __nv_bfloat16* src =
                (half ? Xlp : Xhp) + (size_t)r * FEAT + k0 + q * 8;
            uint32_t dst = sbase + buf * BUF_BYTES + (half ? XLO_OFF : XHI_OFF) +
                           swz(r * 128 + q * 16);
            cp16(dst, src);
        }
        cp_commit();
    };

    float acc[2][3][4];
#pragma unroll
    for (int mt = 0; mt < 2; ++mt)
#pragma unroll
        for (int nt = 0; nt < 3; ++nt)
#pragma unroll
            for (int r = 0; r < 4; ++r) acc[mt][nt][r] = 0.f;

    // per-lane ldmatrix offsets
    const int a_row = lane & 15;
    const int a_colb = (lane >> 4) << 4;                 // 0 or 16 bytes
    // B ldsm4 (n16 x k16): row = n0 + (lane&7) + ((lane>=16)?8:0), col = kb + ((lane>>3)&1)*16
    const int b4_row = (lane & 7) + ((lane >> 4) << 3);
    const int b4_colb = ((lane >> 3) & 1) << 4;
    // B ldsm2 (n8 x k16): lanes 0-15
    const int b2_row = lane & 7;
    const int b2_colb = ((lane >> 3) & 1) << 4;

    // prologue
    stage_w(0);
    cpa_x(0, 0);

    for (int c = 0; c < NCHUNK; ++c) {
        const int buf = c & 1;
        sts_w(buf);
        cp_wait0();
        __syncthreads();
        if (c + 1 < NCHUNK) {
            stage_w(c + 1);
            cpa_x(c + 1, buf ^ 1);
        }

        const uint32_t tb = sbase + buf * BUF_BYTES;
#pragma unroll
        for (int ks = 0; ks < 3; ++ks) {
            const int kb = ks * 32;  // 16 elems * 2B
            unsigned ahi[2][4], alo[2][4];
#pragma unroll
            for (int mt = 0; mt < 2; ++mt) {
                int m0 = warp_m * 32 + mt * 16;
                unsigned off = swz((m0 + a_row) * 128 + kb + a_colb);
                ldsm4(ahi[mt], tb + XHI_OFF + off);
                ldsm4(alo[mt], tb + XLO_OFF + off);
            }
            const int n0 = warp_n * 24;
            unsigned bh[3][2], bl[3][2];
            {
                unsigned off4 = swz((n0 + b4_row) * 128 + kb + b4_colb);
                ldsm4(&bh[0][0], tb + WHI_OFF + off4);   // fills bh[0],bh[1]
                ldsm4(&bl[0][0], tb + WLO_OFF + off4);
                unsigned off2 = swz((n0 + 16 + b2_row) * 128 + kb + b2_colb);
                ldsm2(bh[2], tb + WHI_OFF + off2);
                ldsm2(bl[2], tb + WLO_OFF + off2);
            }
#pragma unroll
            for (int nt = 0; nt < 3; ++nt) {
#pragma unroll
                for (int mt = 0; mt < 2; ++mt) {
                    mma_bf16(acc[mt][nt], ahi[mt], bh[nt]);
                    mma_bf16(acc[mt][nt], ahi[mt], bl[nt]);
                    mma_bf16(acc[mt][nt], alo[mt], bh[nt]);
                }
            }
        }
    }

    // epilogue: bias + sigmoid + store out[b][i][n]
#pragma unroll
    for (int mt = 0; mt < 2; ++mt) {
        int b0 = warp_m * 32 + mt * 16 + (lane >> 2);
#pragma unroll
        for (int nt = 0; nt < 3; ++nt) {
            int n = warp_n * 24 + nt * 8 + 2 * (lane & 3);
            if (n < N_NOTES) {
                float bi0 = bfc[i * N_NOTES + n];
                float bi1 = bfc[i * N_NOTES + n + 1];
                float s0 = acc[mt][nt][0] + bi0;
                float s1 = acc[mt][nt][1] + bi1;
                float s2 = acc[mt][nt][2] + bi0;
                float s3 = acc[mt][nt][3] + bi1;
                float2 r0 = make_float2(1.f / (1.f + __expf(-s0)), 1.f / (1.f + __expf(-s1)));
                float2 r1 = make_float2(1.f / (1.f + __expf(-s2)), 1.f / (1.f + __expf(-s3)));
                *(float2*)(out + ((size_t)b0 * N_INST + i) * N_NOTES + n) = r0;
                *(float2*)(out + ((size_t)(b0 + 8) * N_INST + i) * N_NOTES + n) = r1;
            }
        }
    }
}

// ---------------------------------------------------------------------------
extern "C" void kernel_launch(void* const* d_in, const int* in_sizes, int n_in,
                              void* d_out, int out_size)
{
    const float* data = (const float*)d_in[0];
    const float* w1   = (const float*)d_in[1];
    const float* b1   = (const float*)d_in[2];
    const float* w2   = (const float*)d_in[3];
    const float* b2   = (const float*)d_in[4];
    const float* wfc  = (const float*)d_in[5];
    const float* bfc  = (const float*)d_in[6];
    float* out = (float*)d_out;

    cudaFuncSetAttribute(fc_kernel, cudaFuncAttributeMaxDynamicSharedMemorySize, SMEM_TOTAL);

    conv_kernel<<<2048, 256>>>(data, w1, b1, w2, b2);
    fc_kernel<<<N_INST, 256, SMEM_TOTAL>>>(wfc, bfc, out);
}

// round 5
// speedup vs baseline: 3.4461x; 1.0153x over previous
#include <cuda_runtime.h>
#include <cuda_bf16.h>
#include <cstdint>

// Problem dims
#define N_INST 128
#define N_NOTES 88
#define BATCH 64
#define TLEN 201
#define FLEN 52
#define T1 199
#define F1 50
#define T2 197
#define F2 48
#define FEAT (T2 * F2)  // 9456
#define KC 48
#define NCHUNK 197

typedef unsigned long long ull;

// X split into bf16 hi/lo planes, [i][b][k]
__device__ __nv_bfloat16 g_Xhi[(size_t)N_INST * BATCH * FEAT];
__device__ __nv_bfloat16 g_Xlo[(size_t)N_INST * BATCH * FEAT];

// ---------------------------------------------------------------------------
// helpers
// ---------------------------------------------------------------------------
__device__ __forceinline__ uint32_t smem_u32(const void* p) {
    uint32_t a;
    asm("{ .reg .u64 t; cvta.to.shared.u64 t, %1; cvt.u32.u64 %0, t; }" : "=r"(a) : "l"(p));
    return a;
}
__device__ __forceinline__ unsigned swz(unsigned off) { return off ^ ((off >> 3) & 0x70); }

__device__ __forceinline__ void cp16(uint32_t dst, const void* src) {
    asm volatile("cp.async.ca.shared.global [%0], [%1], 16;" :: "r"(dst), "l"(src) : "memory");
}
__device__ __forceinline__ void cp16g(uint32_t dst, const void* src) {
    asm volatile("cp.async.cg.shared.global [%0], [%1], 16;" :: "r"(dst), "l"(src) : "memory");
}
__device__ __forceinline__ void cp_commit() { asm volatile("cp.async.commit_group;" ::: "memory"); }
#define CP_WAIT(n) asm volatile("cp.async.wait_group %0;" :: "n"(n) : "memory")

__device__ __forceinline__ void ldsm4(unsigned r[4], uint32_t a) {
    asm volatile("ldmatrix.sync.aligned.m8n8.x4.shared.b16 {%0,%1,%2,%3}, [%4];"
                 : "=r"(r[0]), "=r"(r[1]), "=r"(r[2]), "=r"(r[3]) : "r"(a));
}
__device__ __forceinline__ void ldsm2(unsigned r[2], uint32_t a) {
    asm volatile("ldmatrix.sync.aligned.m8n8.x2.shared.b16 {%0,%1}, [%2];"
                 : "=r"(r[0]), "=r"(r[1]) : "r"(a));
}
__device__ __forceinline__ void mma_bf16(float c[4], const unsigned a[4], const unsigned* b) {
    asm volatile(
        "mma.sync.aligned.m16n8k16.row.col.f32.bf16.bf16.f32 "
        "{%0,%1,%2,%3}, {%4,%5,%6,%7}, {%8,%9}, {%0,%1,%2,%3};"
        : "+f"(c[0]), "+f"(c[1]), "+f"(c[2]), "+f"(c[3])
        : "r"(a[0]), "r"(a[1]), "r"(a[2]), "r"(a[3]), "r"(b[0]), "r"(b[1]));
}
__device__ __forceinline__ unsigned cvt_bf16x2(float lo, float hi) {
    unsigned d;
    asm("cvt.rn.bf16x2.f32 %0, %1, %2;" : "=r"(d) : "f"(hi), "f"(lo));
    return d;
}
__device__ __forceinline__ ull pack2(float lo, float hi) {
    ull r;
    asm("mov.b64 %0, {%1, %2};" : "=l"(r) : "f"(lo), "f"(hi));
    return r;
}
__device__ __forceinline__ void unpack2(ull v, float& lo, float& hi) {
    asm("mov.b64 {%0, %1}, %2;" : "=f"(lo), "=f"(hi) : "l"(v));
}
__device__ __forceinline__ ull ffma2(ull a, ull b, ull c) {
    ull d;
    asm("fma.rn.f32x2 %0, %1, %2, %3;" : "=l"(d) : "l"(a), "l"(b), "l"(c));
    return d;
}

// ---------------------------------------------------------------------------
// Conv kernel v2: one warp = (instrument, batch), lane = column PAIR.
// f32x2 packed FMAs (2 cols/lane), 4 shuffles/iter, STG.32 stores.
// ---------------------------------------------------------------------------
__global__ __launch_bounds__(256) void conv_kernel(
    const float* __restrict__ data,
    const float* __restrict__ w1, const float* __restrict__ b1,
    const float* __restrict__ w2, const float* __restrict__ b2)
{
    const int wid = threadIdx.x >> 5;
    const int lane = threadIdx.x & 31;
    const int g = blockIdx.x * 8 + wid;   // 0..8191
    const int b = g & 63;
    const int i = g >> 6;

    const int c0 = 2 * lane;                     // output col pair base
    const int dcol = c0 > 50 ? 50 : c0;          // clamped data col pair
    const bool store_ok = (c0 <= 46);            // conv2 cols c0, c0+1 valid

    ull W1p[9], W2p[9];
#pragma unroll
    for (int k = 0; k < 9; ++k) {
        float a = w1[i * 9 + k]; W1p[k] = pack2(a, a);
        float c = w2[i * 9 + k]; W2p[k] = pack2(c, c);
    }
    const float b1v = b1[i];
    const float b2v = b2[i];
    const ull B1p = pack2(b1v, b1v);
    const ull B2p = pack2(b2v, b2v);

    const float* dptr = data + (size_t)b * TLEN * FLEN;
    unsigned short* xh = (unsigned short*)(g_Xhi + ((size_t)i * BATCH + b) * FEAT);
    unsigned short* xl = (unsigned short*)(g_Xlo + ((size_t)i * BATCH + b) * FEAT);

    // rings: per data row r: a=(d[2l],d[2l+1]) m=(d[2l+1],d[2l+2]) bb=(d[2l+2],d[2l+3])
    ull da[3], dm[3], db[3];
    ull ca[3], cm[3], cb[3];

#define LOAD_ROW(r, slot) do { \
    float2 x = *(const float2*)(dptr + (r) * FLEN + dcol); \
    float n0 = __shfl_down_sync(0xffffffffu, x.x, 1); \
    float n1 = __shfl_down_sync(0xffffffffu, x.y, 1); \
    da[slot] = pack2(x.x, x.y); \
    dm[slot] = pack2(x.y, n0); \
    db[slot] = pack2(n0, n1); \
} while (0)

    LOAD_ROW(0, 0);
    LOAD_ROW(1, 1);
#pragma unroll
    for (int k = 0; k < 3; ++k) { ca[k] = 0; cm[k] = 0; cb[k] = 0; }

#pragma unroll 3
    for (int t = 0; t < T1; ++t) {
        const int s0 = t % 3;
        const int s1 = (t + 1) % 3;
        const int s2 = (t + 2) % 3;

        LOAD_ROW(t + 2, s2);

        // conv1 row t, cols (c0, c0+1)
        ull v = B1p;
        v = ffma2(W1p[0], da[s0], v); v = ffma2(W1p[1], dm[s0], v); v = ffma2(W1p[2], db[s0], v);
        v = ffma2(W1p[3], da[s1], v); v = ffma2(W1p[4], dm[s1], v); v = ffma2(W1p[5], db[s1], v);
        v = ffma2(W1p[6], da[s2], v); v = ffma2(W1p[7], dm[s2], v); v = ffma2(W1p[8], db[s2], v);
        float f0, f1;
        unpack2(v, f0, f1);
        f0 = fmaxf(f0, 0.f); f1 = fmaxf(f1, 0.f);
        float nv0 = __shfl_down_sync(0xffffffffu, f0, 1);
        float nv1 = __shfl_down_sync(0xffffffffu, f1, 1);
        ca[s0] = pack2(f0, f1);
        cm[s0] = pack2(f1, nv0);
        cb[s0] = pack2(nv0, nv1);

        if (t >= 2) {
            // conv2 out row t-2: conv1 rows t-2 (slot s1), t-1 (slot s2), t (slot s0)
            ull u = B2p;
            u = ffma2(W2p[0], ca[s1], u); u = ffma2(W2p[1], cm[s1], u); u = ffma2(W2p[2], cb[s1], u);
            u = ffma2(W2p[3], ca[s2], u); u = ffma2(W2p[4], cm[s2], u); u = ffma2(W2p[5], cb[s2], u);
            u = ffma2(W2p[6], ca[s0], u); u = ffma2(W2p[7], cm[s0], u); u = ffma2(W2p[8], cb[s0], u);
            float u0, u1;
            unpack2(u, u0, u1);
            u0 = fmaxf(u0, 0.f); u1 = fmaxf(u1, 0.f);
            if (store_ok) {
                unsigned ub0 = __float_as_uint(u0), ub1 = __float_as_uint(u1);
                unsigned hi = __byte_perm(ub0, ub1, 0x7632);
                float r0 = u0 - __uint_as_float(ub0 & 0xffff0000u);
                float r1 = u1 - __uint_as_float(ub1 & 0xffff0000u);
                unsigned lo = cvt_bf16x2(r0, r1);
                int idx = (t - 2) * F2 + c0;
                *(unsigned*)(xh + idx) = hi;
                *(unsigned*)(xl + idx) = lo;
            }
        }
    }
#undef LOAD_ROW
}

// ---------------------------------------------------------------------------
// FC kernel v2: one CTA / instrument. mma.sync bf16 3-term hi/lo.
// 4-stage cp.async ring for W fp32 + X bf16; W converted in-smem 1 chunk ahead.
// ---------------------------------------------------------------------------
#define WF32_STAGE 16896                  // 88 rows x 192B
#define WF32_OFF 0
#define X_OFF (4 * WF32_STAGE)            // 67584
#define X_STAGE 16384
#define XLO_REL 8192
#define WB_OFF (X_OFF + 4 * X_STAGE)      // 133120
#define WB_STAGE 24576
#define WLO_REL 12288
#define SMEM_TOTAL (WB_OFF + 2 * WB_STAGE)  // 182272

__global__ __launch_bounds__(256, 1) void fc_kernel(
    const float* __restrict__ wfc,
    const float* __restrict__ bfc,
    float* __restrict__ out)
{
    extern __shared__ char sm[];
    const uint32_t sbase = smem_u32(sm);
    const int i = blockIdx.x;
    const int tid = threadIdx.x;
    const int lane = tid & 31;
    const int wid = tid >> 5;
    const int warp_m = wid >> 2;   // 0..1 -> batch offset *32
    const int warp_n = wid & 3;    // 0..3 -> note offset *24

    // zero bf16-W buffers once (pad rows 88..95 never overwritten)
    for (int o = tid * 16; o < 2 * WB_STAGE; o += 256 * 16)
        *(uint4*)(sm + WB_OFF + o) = make_uint4(0, 0, 0, 0);

    const float* Wp = wfc + (size_t)i * N_NOTES * FEAT;
    const __nv_bfloat16* Xhp = g_Xhi + (size_t)i * BATCH * FEAT;
    const __nv_bfloat16* Xlp = g_Xlo + (size_t)i * BATCH * FEAT;

    // prefetch chunk c into ring stage c&3 (W fp32 1056 cp16 + X 768 cp16)
    auto prefetch = [&](int c) {
        const int k0 = c * KC;
        const int st = c & 3;
        const uint32_t wdst = sbase + WF32_OFF + st * WF32_STAGE;
#pragma unroll
        for (int s = 0; s < 4; ++s) {
            int idx = tid + s * 256;
            int row = idx / 12, q = idx % 12;
            cp16g(wdst + idx * 16, Wp + (size_t)row * FEAT + k0 + q * 4);
        }
        if (tid < 32) {
            int idx = 1024 + tid;
            int row = idx / 12, q = idx % 12;
            cp16g(wdst + idx * 16, Wp + (size_t)row * FEAT + k0 + q * 4);
        }
        const uint32_t xdst = sbase + X_OFF + st * X_STAGE;
#pragma unroll
        for (int s = 0; s < 3; ++s) {
            int idx = tid + s * 256;
            int half = idx >= 384;
            int e = half ? idx - 384 : idx;
            int r = e / 6, q = e % 6;
            const __nv_bfloat16* src = (half ? Xlp : Xhp) + (size_t)r * FEAT + k0 + q * 8;
            cp16(xdst + (half ? XLO_REL : 0) + swz(r * 128 + q * 16), src);
        }
        cp_commit();
    };

    // convert W fp32 stage (c&3) -> bf16 hi/lo buffer (c&1)
    auto convert = [&](int c) {
        const char* src = sm + WF32_OFF + (c & 3) * WF32_STAGE;
        char* dhi = sm + WB_OFF + (c & 1) * WB_STAGE;
        char* dlo = dhi + WLO_REL;
#pragma unroll
        for (int s = 0; s < 5; ++s) {
            int idx = tid + s * 256;
            if (idx < 1056) {
                int row = idx / 12, q = idx % 12;
                float4 v = *(const float4*)(src + idx * 16);
                unsigned ax = __float_as_uint(v.x), ay = __float_as_uint(v.y);
                unsigned az = __float_as_uint(v.z), aw = __float_as_uint(v.w);
                unsigned hi0 = __byte_perm(ax, ay, 0x7632);
                unsigned hi1 = __byte_perm(az, aw, 0x7632);
                float rx = v.x - __uint_as_float(ax & 0xffff0000u);
                float ry = v.y - __uint_as_float(ay & 0xffff0000u);
                float rz = v.z - __uint_as_float(az & 0xffff0000u);
                float rw = v.w - __uint_as_float(aw & 0xffff0000u);
                unsigned lo0 = cvt_bf16x2(rx, ry);
                unsigned lo1 = cvt_bf16x2(rz, rw);
                unsigned off = swz(row * 128 + q * 8);
                *(uint2*)(dhi + off) = make_uint2(hi0, hi1);
                *(uint2*)(dlo + off) = make_uint2(lo0, lo1);
            }
        }
    };

    float acc[2][3][4];
#pragma unroll
    for (int mt = 0; mt < 2; ++mt)
#pragma unroll
        for (int nt = 0; nt < 3; ++nt)
#pragma unroll
            for (int r = 0; r < 4; ++r) acc[mt][nt][r] = 0.f;

    // per-lane ldmatrix offsets
    const int a_row = lane & 15;
    const int a_colb = (lane >> 4) << 4;
    const int b4_row = (lane & 7) + ((lane >> 4) << 3);
    const int b4_colb = ((lane >> 3) & 1) << 4;
    const int b2_row = lane & 7;
    const int b2_colb = ((lane >> 3) & 1) << 4;

    // prologue: 3 stages in flight, convert chunk 0
    prefetch(0); prefetch(1); prefetch(2);
    CP_WAIT(2);
    __syncthreads();
    convert(0);

    for (int c = 0; c < NCHUNK; ++c) {
        if (c + 3 < NCHUNK) prefetch(c + 3);
        if (c < NCHUNK - 3)      CP_WAIT(2);
        else if (c == NCHUNK - 3) CP_WAIT(1);
        else                      CP_WAIT(0);
        __syncthreads();
        if (c + 1 < NCHUNK) convert(c + 1);

        const uint32_t xb = sbase + X_OFF + (c & 3) * X_STAGE;
        const uint32_t wb = sbase + WB_OFF + (c & 1) * WB_STAGE;
#pragma unroll
        for (int ks = 0; ks < 3; ++ks) {
            const int kb = ks * 32;
            unsigned ahi[2][4], alo[2][4];
#pragma unroll
            for (int mt = 0; mt < 2; ++mt) {
                int m0 = warp_m * 32 + mt * 16;
                unsigned off = swz((m0 + a_row) * 128 + kb + a_colb);
                ldsm4(ahi[mt], xb + off);
                ldsm4(alo[mt], xb + XLO_REL + off);
            }
            const int n0 = warp_n * 24;
            unsigned bh[3][2], bl[3][2];
            {
                unsigned off4 = swz((n0 + b4_row) * 128 + kb + b4_colb);
                ldsm4(&bh[0][0], wb + off4);
                ldsm4(&bl[0][0], wb + WLO_REL + off4);
                unsigned off2 = swz((n0 + 16 + b2_row) * 128 + kb + b2_colb);
                ldsm2(bh[2], wb + off2);
                ldsm2(bl[2], wb + WLO_REL + off2);
            }
#pragma unroll
            for (int nt = 0; nt < 3; ++nt) {
#pragma unroll
                for (int mt = 0; mt < 2; ++mt) {
                    mma_bf16(acc[mt][nt], ahi[mt], bh[nt]);
                    mma_bf16(acc[mt][nt], ahi[mt], bl[nt]);
                    mma_bf16(acc[mt][nt], alo[mt], bh[nt]);
                }
            }
        }
    }

    // epilogue: bias + sigmoid + store out[b][i][n]
#pragma unroll
    for (int mt = 0; mt < 2; ++mt) {
        int b0 = warp_m * 32 + mt * 16 + (lane >> 2);
#pragma unroll
        for (int nt = 0; nt < 3; ++nt) {
            int n = warp_n * 24 + nt * 8 + 2 * (lane & 3);
            if (n < N_NOTES) {
                float bi0 = bfc[i * N_NOTES + n];
                float bi1 = bfc[i * N_NOTES + n + 1];
                float s0 = acc[mt][nt][0] + bi0;
                float s1 = acc[mt][nt][1] + bi1;
                float s2 = acc[mt][nt][2] + bi0;
                float s3 = acc[mt][nt][3] + bi1;
                float2 r0 = make_float2(1.f / (1.f + __expf(-s0)), 1.f / (1.f + __expf(-s1)));
                float2 r1 = make_float2(1.f / (1.f + __expf(-s2)), 1.f / (1.f + __expf(-s3)));
                *(float2*)(out + ((size_t)b0 * N_INST + i) * N_NOTES + n) = r0;
                *(float2*)(out + ((size_t)(b0 + 8) * N_INST + i) * N_NOTES + n) = r1;
            }
        }
    }
}

// ---------------------------------------------------------------------------
extern "C" void kernel_launch(void* const* d_in, const int* in_sizes, int n_in,
                              void* d_out, int out_size)
{
    const float* data = (const float*)d_in[0];
    const float* w1   = (const float*)d_in[1];
    const float* b1   = (const float*)d_in[2];
    const float* w2   = (const float*)d_in[3];
    const float* b2   = (const float*)d_in[4];
    const float* wfc  = (const float*)d_in[5];
    const float* bfc  = (const float*)d_in[6];
    float* out = (float*)d_out;

    cudaFuncSetAttribute(fc_kernel, cudaFuncAttributeMaxDynamicSharedMemorySize, SMEM_TOTAL);

    conv_kernel<<<1024, 256>>>(data, w1, b1, w2, b2);
    fc_kernel<<<N_INST, 256, SMEM_TOTAL>>>(wfc, bfc, out);
}

// round 6
// speedup vs baseline: 4.0237x; 1.1676x over previous
#include <cuda_runtime.h>
#include <cuda_bf16.h>
#include <cstdint>

// Problem dims
#define N_INST 128
#define N_NOTES 88
#define BATCH 64
#define TLEN 201
#define FLEN 52
#define T1 199
#define F1 50
#define T2 197
#define F2 48
#define FEAT (T2 * F2)  // 9456
#define KC 48
#define NCHUNK 197

typedef unsigned long long ull;

// ---------------------------------------------------------------------------
// smem layout
// ---------------------------------------------------------------------------
#define WF32_STAGE 16896                  // 88 rows x 192B fp32 W
#define WF32_OFF 0
#define WB_OFF (4 * WF32_STAGE)           // 67584: bf16 W hi/lo double buffer
#define WB_STAGE 24576
#define WLO_REL 12288
#define C1_SLOT (64 * FLEN * 4)           // 13312: one conv1 row, all 64 batches
#define C1_OFF (WB_OFF + 2 * WB_STAGE)    // 116736
#define X_OFF (C1_OFF + 3 * C1_SLOT)      // 156672: single X tile (hi+lo)
#define XLO_REL 8192
#define SMEM_TOTAL (X_OFF + 16384)        // 173056

// ---------------------------------------------------------------------------
// helpers
// ---------------------------------------------------------------------------
__device__ __forceinline__ uint32_t smem_u32(const void* p) {
    uint32_t a;
    asm("{ .reg .u64 t; cvta.to.shared.u64 t, %1; cvt.u32.u64 %0, t; }" : "=r"(a) : "l"(p));
    return a;
}
__device__ __forceinline__ unsigned swz(unsigned off) { return off ^ ((off >> 3) & 0x70); }

__device__ __forceinline__ void cp16g(uint32_t dst, const void* src) {
    asm volatile("cp.async.cg.shared.global [%0], [%1], 16;" :: "r"(dst), "l"(src) : "memory");
}
__device__ __forceinline__ void cp_commit() { asm volatile("cp.async.commit_group;" ::: "memory"); }
#define CP_WAIT(n) asm volatile("cp.async.wait_group %0;" :: "n"(n) : "memory")

__device__ __forceinline__ void ldsm4(unsigned r[4], uint32_t a) {
    asm volatile("ldmatrix.sync.aligned.m8n8.x4.shared.b16 {%0,%1,%2,%3}, [%4];"
                 : "=r"(r[0]), "=r"(r[1]), "=r"(r[2]), "=r"(r[3]) : "r"(a));
}
__device__ __forceinline__ void ldsm2(unsigned r[2], uint32_t a) {
    asm volatile("ldmatrix.sync.aligned.m8n8.x2.shared.b16 {%0,%1}, [%2];"
                 : "=r"(r[0]), "=r"(r[1]) : "r"(a));
}
__device__ __forceinline__ void mma_bf16(float c[4], const unsigned a[4], const unsigned* b) {
    asm volatile(
        "mma.sync.aligned.m16n8k16.row.col.f32.bf16.bf16.f32 "
        "{%0,%1,%2,%3}, {%4,%5,%6,%7}, {%8,%9}, {%0,%1,%2,%3};"
        : "+f"(c[0]), "+f"(c[1]), "+f"(c[2]), "+f"(c[3])
        : "r"(a[0]), "r"(a[1]), "r"(a[2]), "r"(a[3]), "r"(b[0]), "r"(b[1]));
}
__device__ __forceinline__ unsigned cvt_bf16x2(float lo, float hi) {
    unsigned d;
    asm("cvt.rn.bf16x2.f32 %0, %1, %2;" : "=r"(d) : "f"(hi), "f"(lo));
    return d;
}
__device__ __forceinline__ ull pack2(float lo, float hi) {
    ull r;
    asm("mov.b64 %0, {%1, %2};" : "=l"(r) : "f"(lo), "f"(hi));
    return r;
}
__device__ __forceinline__ void unpack2(ull v, float& lo, float& hi) {
    asm("mov.b64 {%0, %1}, %2;" : "=f"(lo), "=f"(hi) : "l"(v));
}
__device__ __forceinline__ ull ffma2(ull a, ull b, ull c) {
    ull d;
    asm("fma.rn.f32x2 %0, %1, %2, %3;" : "=l"(d) : "l"(a), "l"(b), "l"(c));
    return d;
}
__device__ __forceinline__ float4 lds128(uint32_t a) {
    float4 v;
    asm volatile("ld.shared.v4.f32 {%0,%1,%2,%3}, [%4];"
                 : "=f"(v.x), "=f"(v.y), "=f"(v.z), "=f"(v.w) : "r"(a));
    return v;
}
__device__ __forceinline__ void sts64(uint32_t a, ull v) {
    asm volatile("st.shared.b64 [%0], %1;" :: "r"(a), "l"(v) : "memory");
}

// load 16 data floats (one row segment) into packed E/O pair arrays
__device__ __forceinline__ void load_row(const float* p, ull* E, ull* O) {
    float4 a = *(const float4*)p;
    float4 b = *(const float4*)(p + 4);
    float4 c = *(const float4*)(p + 8);
    float4 d = *(const float4*)(p + 12);
    E[0] = pack2(a.x, a.y); E[1] = pack2(a.z, a.w);
    E[2] = pack2(b.x, b.y); E[3] = pack2(b.z, b.w);
    E[4] = pack2(c.x, c.y); E[5] = pack2(c.z, c.w);
    E[6] = pack2(d.x, d.y); E[7] = pack2(d.z, d.w);
    O[0] = pack2(a.y, a.z); O[1] = pack2(a.w, b.x);
    O[2] = pack2(b.y, b.z); O[3] = pack2(b.w, c.x);
    O[4] = pack2(c.y, c.z); O[5] = pack2(c.w, d.x);
    O[6] = pack2(d.y, d.z);
}

// 3x3 conv on packed pairs: output pair q from rows A,B,C
template <int SA, int SB, int SC>
__device__ __forceinline__ void conv1_step(
    const ull E[3][8], const ull O[3][7],
    const ull* W1p, ull B1p, int nq1, uint32_t sts_base)
{
#pragma unroll
    for (int q = 0; q < 7; ++q) {
        ull v = B1p;
        v = ffma2(W1p[0], E[SA][q], v); v = ffma2(W1p[1], O[SA][q], v); v = ffma2(W1p[2], E[SA][q + 1], v);
        v = ffma2(W1p[3], E[SB][q], v); v = ffma2(W1p[4], O[SB][q], v); v = ffma2(W1p[5], E[SB][q + 1], v);
        v = ffma2(W1p[6], E[SC][q], v); v = ffma2(W1p[7], O[SC][q], v); v = ffma2(W1p[8], E[SC][q + 1], v);
        float f0, f1;
        unpack2(v, f0, f1);
        f0 = fmaxf(f0, 0.f); f1 = fmaxf(f1, 0.f);
        if (q < nq1) sts64(sts_base + q * 8, pack2(f0, f1));
    }
}

// one conv2 input row (16 cols from smem) accumulated into 6 output pairs
__device__ __forceinline__ void c2row(ull u[6], uint32_t a, const ull* W) {
    float4 g0 = lds128(a), g1 = lds128(a + 16), g2 = lds128(a + 32), g3 = lds128(a + 48);
    ull e0 = pack2(g0.x, g0.y), e1 = pack2(g0.z, g0.w), e2 = pack2(g1.x, g1.y),
        e3 = pack2(g1.z, g1.w), e4 = pack2(g2.x, g2.y), e5 = pack2(g2.z, g2.w),
        e6 = pack2(g3.x, g3.y);
    ull o0 = pack2(g0.y, g0.z), o1 = pack2(g0.w, g1.x), o2 = pack2(g1.y, g1.z),
        o3 = pack2(g1.w, g2.x), o4 = pack2(g2.y, g2.z), o5 = pack2(g2.w, g3.x);
    u[0] = ffma2(W[0], e0, u[0]); u[0] = ffma2(W[1], o0, u[0]); u[0] = ffma2(W[2], e1, u[0]);
    u[1] = ffma2(W[0], e1, u[1]); u[1] = ffma2(W[1], o1, u[1]); u[1] = ffma2(W[2], e2, u[1]);
    u[2] = ffma2(W[0], e2, u[2]); u[2] = ffma2(W[1], o2, u[2]); u[2] = ffma2(W[2], e3, u[2]);
    u[3] = ffma2(W[0], e3, u[3]); u[3] = ffma2(W[1], o3, u[3]); u[3] = ffma2(W[2], e4, u[3]);
    u[4] = ffma2(W[0], e4, u[4]); u[4] = ffma2(W[1], o4, u[4]); u[4] = ffma2(W[2], e5, u[4]);
    u[5] = ffma2(W[0], e5, u[5]); u[5] = ffma2(W[1], o5, u[5]); u[5] = ffma2(W[2], e6, u[5]);
}

// ---------------------------------------------------------------------------
// Fused kernel: one CTA per instrument. Conv feeds the MMA X-tile in smem.
// ---------------------------------------------------------------------------
__global__ __launch_bounds__(256, 1) void fused_kernel(
    const float* __restrict__ data,
    const float* __restrict__ w1, const float* __restrict__ b1,
    const float* __restrict__ w2, const float* __restrict__ b2,
    const float* __restrict__ wfc,
    const float* __restrict__ bfc,
    float* __restrict__ out)
{
    extern __shared__ char sm[];
    const uint32_t sbase = smem_u32(sm);
    const int i = blockIdx.x;
    const int tid = threadIdx.x;
    const int lane = tid & 31;
    const int wid = tid >> 5;
    const int warp_m = wid >> 2;
    const int warp_n = wid & 3;

    // conv thread identity
    const int cb = tid >> 2;       // batch 0..63
    const int fg = tid & 3;        // column group
    const int nq1 = (fg == 3) ? 7 : 6;

    // zero bf16-W buffers once (pad rows 88..95 stay zero)
    for (int o = tid * 16; o < 2 * WB_STAGE; o += 256 * 16)
        *(uint4*)(sm + WB_OFF + o) = make_uint4(0, 0, 0, 0);

    // conv weights, packed-splat
    ull W1p[9], W2p[9];
#pragma unroll
    for (int k = 0; k < 9; ++k) {
        float a = w1[i * 9 + k]; W1p[k] = pack2(a, a);
        float c = w2[i * 9 + k]; W2p[k] = pack2(c, c);
    }
    float b1v = b1[i], b2v = b2[i];
    const ull B1p = pack2(b1v, b1v);
    const ull B2p = pack2(b2v, b2v);

    const float* dptr = data + (size_t)cb * TLEN * FLEN + 12 * fg;
    const uint32_t c1base = sbase + C1_OFF + cb * (FLEN * 4) + 48 * fg;

    const float* Wp = wfc + (size_t)i * N_NOTES * FEAT;

    // --- W cp.async pipeline pieces ---
    auto prefetchW = [&](int c) {
        const int k0 = c * KC;
        const uint32_t wdst = sbase + WF32_OFF + (c & 3) * WF32_STAGE;
#pragma unroll
        for (int s = 0; s < 4; ++s) {
            int idx = tid + s * 256;
            cp16g(wdst + idx * 16, Wp + (size_t)(idx / 12) * FEAT + k0 + (idx % 12) * 4);
        }
        if (tid < 32) {
            int idx = 1024 + tid;
            cp16g(wdst + idx * 16, Wp + (size_t)(idx / 12) * FEAT + k0 + (idx % 12) * 4);
        }
        cp_commit();
    };
    auto convertW = [&](int c) {
        const char* src = sm + WF32_OFF + (c & 3) * WF32_STAGE;
        char* dhi = sm + WB_OFF + (c & 1) * WB_STAGE;
        char* dlo = dhi + WLO_REL;
#pragma unroll
        for (int s = 0; s < 5; ++s) {
            int idx = tid + s * 256;
            if (idx < 1056) {
                int row = idx / 12, q = idx % 12;
                float4 v = *(const float4*)(src + idx * 16);
                unsigned ax = __float_as_uint(v.x), ay = __float_as_uint(v.y);
                unsigned az = __float_as_uint(v.z), aw = __float_as_uint(v.w);
                unsigned hi0 = __byte_perm(ax, ay, 0x7632);
                unsigned hi1 = __byte_perm(az, aw, 0x7632);
                float rx = v.x - __uint_as_float(ax & 0xffff0000u);
                float ry = v.y - __uint_as_float(ay & 0xffff0000u);
                float rz = v.z - __uint_as_float(az & 0xffff0000u);
                float rw = v.w - __uint_as_float(aw & 0xffff0000u);
                unsigned lo0 = cvt_bf16x2(rx, ry);
                unsigned lo1 = cvt_bf16x2(rz, rw);
                unsigned off = swz(row * 128 + q * 8);
                *(uint2*)(dhi + off) = make_uint2(hi0, hi1);
                *(uint2*)(dlo + off) = make_uint2(lo0, lo1);
            }
        }
    };

    // --- conv2 + X-tile write ---
    auto conv2_step = [&](int c) {
        uint32_t a0 = c1base + (c % 3) * C1_SLOT;
        uint32_t a1 = c1base + ((c + 1) % 3) * C1_SLOT;
        uint32_t a2 = c1base + ((c + 2) % 3) * C1_SLOT;
        ull u[6];
#pragma unroll
        for (int q = 0; q < 6; ++q) u[q] = B2p;
        c2row(u, a0, W2p + 0);
        c2row(u, a1, W2p + 3);
        c2row(u, a2, W2p + 6);
        unsigned hi[6], lo[6];
#pragma unroll
        for (int q = 0; q < 6; ++q) {
            float f0, f1;
            unpack2(u[q], f0, f1);
            f0 = fmaxf(f0, 0.f); f1 = fmaxf(f1, 0.f);
            unsigned ub0 = __float_as_uint(f0), ub1 = __float_as_uint(f1);
            hi[q] = __byte_perm(ub0, ub1, 0x7632);
            float r0 = f0 - __uint_as_float(ub0 & 0xffff0000u);
            float r1 = f1 - __uint_as_float(ub1 & 0xffff0000u);
            lo[q] = cvt_bf16x2(r0, r1);
        }
        const uint32_t xa = sbase + X_OFF;
#pragma unroll
        for (int r = 0; r < 3; ++r) {
            unsigned off = swz(cb * 128 + 24 * fg + 8 * r);
            sts64(xa + off, (ull)hi[2 * r] | ((ull)hi[2 * r + 1] << 32));
            sts64(xa + XLO_REL + off, (ull)lo[2 * r] | ((ull)lo[2 * r + 1] << 32));
        }
    };

    // --- MMA ---
    float acc[2][3][4];
#pragma unroll
    for (int mt = 0; mt < 2; ++mt)
#pragma unroll
        for (int nt = 0; nt < 3; ++nt)
#pragma unroll
            for (int r = 0; r < 4; ++r) acc[mt][nt][r] = 0.f;

    const int a_row = lane & 15;
    const int a_colb = (lane >> 4) << 4;
    const int b4_row = (lane & 7) + ((lane >> 4) << 3);
    const int b4_colb = ((lane >> 3) & 1) << 4;
    const int b2_row = lane & 7;
    const int b2_colb = ((lane >> 3) & 1) << 4;

    auto mma_step = [&](int c) {
        const uint32_t xb = sbase + X_OFF;
        const uint32_t wb = sbase + WB_OFF + (c & 1) * WB_STAGE;
#pragma unroll
        for (int ks = 0; ks < 3; ++ks) {
            const int kb = ks * 32;
            unsigned ahi[2][4], alo[2][4];
#pragma unroll
            for (int mt = 0; mt < 2; ++mt) {
                int m0 = warp_m * 32 + mt * 16;
                unsigned off = swz((m0 + a_row) * 128 + kb + a_colb);
                ldsm4(ahi[mt], xb + off);
                ldsm4(alo[mt], xb + XLO_REL + off);
            }
            const int n0 = warp_n * 24;
            unsigned bh[3][2], bl[3][2];
            unsigned off4 = swz((n0 + b4_row) * 128 + kb + b4_colb);
            ldsm4(&bh[0][0], wb + off4);
            ldsm4(&bl[0][0], wb + WLO_REL + off4);
            unsigned off2 = swz((n0 + 16 + b2_row) * 128 + kb + b2_colb);
            ldsm2(bh[2], wb + off2);
            ldsm2(bl[2], wb + WLO_REL + off2);
#pragma unroll
            for (int nt = 0; nt < 3; ++nt)
#pragma unroll
                for (int mt = 0; mt < 2; ++mt) {
                    mma_bf16(acc[mt][nt], ahi[mt], bh[nt]);
                    mma_bf16(acc[mt][nt], ahi[mt], bl[nt]);
                    mma_bf16(acc[mt][nt], alo[mt], bh[nt]);
                }
        }
    };

    // --- prologue ---
    ull E[3][8], O[3][7];
    prefetchW(0); prefetchW(1); prefetchW(2);

    load_row(dptr + 0 * FLEN, E[0], O[0]);
    load_row(dptr + 1 * FLEN, E[1], O[1]);
    load_row(dptr + 2 * FLEN, E[2], O[2]);
    conv1_step<0, 1, 2>(E, O, W1p, B1p, nq1, c1base + 0 * C1_SLOT);
    load_row(dptr + 3 * FLEN, E[0], O[0]);
    conv1_step<1, 2, 0>(E, O, W1p, B1p, nq1, c1base + 1 * C1_SLOT);

    CP_WAIT(2);
    __syncthreads();
    convertW(0);

#define BODY(c, SN, SA, SB, SC) do { \
    if ((c) + 3 < NCHUNK) prefetchW((c) + 3); \
    load_row(dptr + ((c) + 4) * FLEN, E[SN], O[SN]); \
    conv1_step<SA, SB, SC>(E, O, W1p, B1p, nq1, c1base + (((c) + 2) % 3) * C1_SLOT); \
    if ((c) < NCHUNK - 3) { CP_WAIT(2); } \
    else if ((c) == NCHUNK - 3) { CP_WAIT(1); } \
    else { CP_WAIT(0); } \
    __syncthreads(); \
    if ((c) + 1 < NCHUNK) convertW((c) + 1); \
    conv2_step((c)); \
    __syncthreads(); \
    mma_step((c)); \
} while (0)

    for (int c0 = 0; c0 < 195; c0 += 3) {
        BODY(c0 + 0, 1, 2, 0, 1);
        BODY(c0 + 1, 2, 0, 1, 2);
        BODY(c0 + 2, 0, 1, 2, 0);
    }
    BODY(195, 1, 2, 0, 1);
    BODY(196, 2, 0, 1, 2);
#undef BODY

    // --- epilogue: bias + sigmoid + store out[b][i][n] ---
#pragma unroll
    for (int mt = 0; mt < 2; ++mt) {
        int b0 = warp_m * 32 + mt * 16 + (lane >> 2);
#pragma unroll
        for (int nt = 0; nt < 3; ++nt) {
            int n = warp_n * 24 + nt * 8 + 2 * (lane & 3);
            if (n < N_NOTES) {
                float bi0 = bfc[i * N_NOTES + n];
                float bi1 = bfc[i * N_NOTES + n + 1];
                float s0 = acc[mt][nt][0] + bi0;
                float s1 = acc[mt][nt][1] + bi1;
                float s2 = acc[mt][nt][2] + bi0;
                float s3 = acc[mt][nt][3] + bi1;
                float2 r0 = make_float2(1.f / (1.f + __expf(-s0)), 1.f / (1.f + __expf(-s1)));
                float2 r1 = make_float2(1.f / (1.f + __expf(-s2)), 1.f / (1.f + __expf(-s3)));
                *(float2*)(out + ((size_t)b0 * N_INST + i) * N_NOTES + n) = r0;
                *(float2*)(out + ((size_t)(b0 + 8) * N_INST + i) * N_NOTES + n) = r1;
            }
        }
    }
}

// ---------------------------------------------------------------------------
extern "C" void kernel_launch(void* const* d_in, const int* in_sizes, int n_in,
                              void* d_out, int out_size)
{
    const float* data = (const float*)d_in[0];
    const float* w1   = (const float*)d_in[1];
    const float* b1   = (const float*)d_in[2];
    const float* w2   = (const float*)d_in[3];
    const float* b2   = (const float*)d_in[4];
    const float* wfc  = (const float*)d_in[5];
    const float* bfc  = (const float*)d_in[6];
    float* out = (float*)d_out;

    cudaFuncSetAttribute(fused_kernel, cudaFuncAttributeMaxDynamicSharedMemorySize, SMEM_TOTAL);
    fused_kernel<<<N_INST, 256, SMEM_TOTAL>>>(data, w1, b1, w2, b2, wfc, bfc, out);
}